// round 5
// baseline (speedup 1.0000x reference)
#include <cuda_runtime.h>
#include <cstdint>

// ---------------------------------------------------------------------------
// MDescAug: per-query candidate reranking with descriptor augmentation.
//   X: [50000,512] f32,  Q: [100,512] f32,  ranks: [50000,100] i32/i64 (probed)
// Output f32 concat: rerank_final[100,400], res_top[100,400], pre[100,400],
//                    x_dba[100,400,512]
// GEMM: serial-k fp32 FMA chains (bitwise == round-1 FFMA bracketing),
// packed 2 output columns per fma.rn.f32x2 (FFMA2) for 2x fp32 throughput.
// Round-5 fix: A-dup smem slice stride AS 132 -> 156 (swizzle overflow).
// ---------------------------------------------------------------------------

#define NDB  50000
#define NQ   100
#define DIM  512
#define MM   400
#define MPAD 448              // 7 * 64, zero-padded rows
#define KTOP 10
#define BETA 0.15f

#define OFF_RERANK 0
#define OFF_RESTOP 40000
#define OFF_PRE    80000
#define OFF_XDBA   120000
#define FULL_OUT   20600000

// Scratch (device globals; no allocation allowed)
__device__ float g_Xs[(size_t)NQ * MPAD * DIM];   // gathered (padded)
__device__ float g_S[(size_t)NQ * MM * MM];       // similarity matrices
__device__ int   g_rt[NQ * MM];
__device__ int   g_idx[NQ * MM * KTOP];
__device__ float g_vals[NQ * MM * KTOP];
__device__ float g_restop[NQ * MM];
__device__ int   g_is64;

// ---- order-preserving float<->uint ------------------------------------------
__device__ __forceinline__ unsigned int ordf(float f) {
    unsigned int u = __float_as_uint(f);
    return (u & 0x80000000u) ? ~u : (u | 0x80000000u);
}
__device__ __forceinline__ float unordf(unsigned int o) {
    return __uint_as_float((o & 0x80000000u) ? (o & 0x7FFFFFFFu) : ~o);
}
__device__ __forceinline__ unsigned long long pack_key(float v, int idx) {
    return ((unsigned long long)ordf(v) << 32) |
           (unsigned long long)(0xFFFFFFFFu - (unsigned int)idx);
}

// ---- probe: int64 vs int32 ranks --------------------------------------------
__global__ void probe_kernel(const int* __restrict__ r) {
    __shared__ int cnt;
    if (threadIdx.x == 0) cnt = 0;
    __syncthreads();
    int nz = 0;
    for (int i = threadIdx.x; i < 1024; i += blockDim.x)
        nz += (r[2 * i + 1] != 0);
    atomicAdd(&cnt, nz);
    __syncthreads();
    if (threadIdx.x == 0) g_is64 = (cnt < 100) ? 1 : 0;
}

// ---- gather Xs[q][m][:] = X[ranks[m][q]][:]; zero-pad rows 400..447 ---------
__global__ __launch_bounds__(128) void gather_kernel(const float* __restrict__ X,
                                                     const void* __restrict__ ranks) {
    int m = blockIdx.x, q = blockIdx.y, tid = threadIdx.x;
    float4* dst = (float4*)(g_Xs + ((size_t)q * MPAD + m) * DIM);
    if (m >= MM) {
        dst[tid] = make_float4(0.f, 0.f, 0.f, 0.f);
        return;
    }
    int rid;
    if (g_is64) rid = (int)((const long long*)ranks)[(size_t)m * NQ + q];
    else        rid = ((const int*)ranks)[(size_t)m * NQ + q];
    if (tid == 0) g_rt[q * MM + m] = rid;
    const float4* src = (const float4*)(X + (size_t)rid * DIM);
    dst[tid] = src[tid];
}

// ---- packed fp32 helpers ----------------------------------------------------
__device__ __forceinline__ unsigned long long pack_ff(float lo, float hi) {
    unsigned long long r;
    asm("mov.b64 %0, {%1, %2};" : "=l"(r) : "f"(lo), "f"(hi));
    return r;
}
__device__ __forceinline__ void unpack_ff(unsigned long long v, float& lo, float& hi) {
    asm("mov.b64 {%0, %1}, %2;" : "=f"(lo), "=f"(hi) : "l"(v));
}
// Two independent IEEE fp32 FMAs (FFMA2). Each lane = exact fp32 fma chain.
__device__ __forceinline__ void ffma2(unsigned long long& acc,
                                      unsigned long long a, unsigned long long b) {
    asm("fma.rn.f32x2 %0, %1, %2, %0;" : "+l"(acc) : "l"(a), "l"(b));
}

// ---- batched symmetric GEMM: S_q = Xs_q * Xs_q^T ----------------------------
// 64x64 tile, 64 threads, per-thread 8 rows x 8 cols (4 col-pairs packed).
// Serial k-ascending fp32 chains, bitwise-identical to scalar FFMA GEMM.
#define AS 156   // words per k-slice of A-dup: 64 rows*2 + max swizzle 28
#define BS 68    // words per k-slice of B: 64 cols + swizzle room
__global__ __launch_bounds__(64) void gemm_kernel() {
    __shared__ __align__(16) float Ad[32 * AS];  // A duplicated {a,a}, swizzled
    __shared__ __align__(16) float Bb[32 * BS];  // B scalar, swizzled

    int p = blockIdx.x, q = blockIdx.y;
    int bi = 0, bj = 0;
    {
        int t = 0;
        #pragma unroll
        for (int i = 0; i < 7; i++) {
            int c = 7 - i;
            if (p < t + c) { bi = i; bj = i + (p - t); break; }
            t += c;
        }
    }
    const float* Xq = g_Xs + (size_t)q * MPAD * DIM;
    const float* Ap = Xq + (size_t)bi * 64 * DIM;
    const float* Bp = Xq + (size_t)bj * 64 * DIM;

    int tid = threadIdx.x;
    int ty = tid >> 3, tx = tid & 7;  // 8x8 thread grid

    unsigned long long acc[8][4];
    #pragma unroll
    for (int r = 0; r < 8; r++)
        #pragma unroll
        for (int c = 0; c < 4; c++) acc[r][c] = 0ULL;

    // staging pointers: thread t stages row t of both tiles
    const float4* Ag = (const float4*)(Ap + (size_t)tid * DIM);
    const float4* Bg = (const float4*)(Bp + (size_t)tid * DIM);
    int aswz = 2 * tid + 4 * (tid >> 3);   // A-dup word offset for row tid (max 154)
    int bswz = tid + 2 * (tid >> 5);       // B word offset for col tid (max 65)

    for (int ch = 0; ch < 16; ch++) {
        float4 va[8], vb[8];
        #pragma unroll
        for (int i = 0; i < 8; i++) { va[i] = Ag[ch * 8 + i]; vb[i] = Bg[ch * 8 + i]; }
        __syncthreads();
        #pragma unroll
        for (int i = 0; i < 8; i++) {
            float a4[4] = {va[i].x, va[i].y, va[i].z, va[i].w};
            float b4[4] = {vb[i].x, vb[i].y, vb[i].z, vb[i].w};
            #pragma unroll
            for (int j = 0; j < 4; j++) {
                int k = i * 4 + j;
                *(unsigned long long*)&Ad[k * AS + aswz] = pack_ff(a4[j], a4[j]);
                Bb[k * BS + bswz] = b4[j];
            }
        }
        __syncthreads();
        #pragma unroll
        for (int kk = 0; kk < 32; kk++) {
            unsigned long long af[8], bf[4];
            #pragma unroll
            for (int rr = 0; rr < 8; rr++)
                af[rr] = *(const unsigned long long*)&Ad[kk * AS + 20 * ty + 2 * rr];
            #pragma unroll
            for (int cp = 0; cp < 4; cp++)
                bf[cp] = *(const unsigned long long*)&Bb[kk * BS + 8 * tx + 2 * cp + 2 * (tx >> 2)];
            #pragma unroll
            for (int rr = 0; rr < 8; rr++)
                #pragma unroll
                for (int cp = 0; cp < 4; cp++)
                    ffma2(acc[rr][cp], af[rr], bf[cp]);
        }
    }

    float* S = g_S + (size_t)q * MM * MM;
    #pragma unroll
    for (int rr = 0; rr < 8; rr++) {
        int r0 = bi * 64 + ty * 8 + rr;
        #pragma unroll
        for (int cp = 0; cp < 4; cp++) {
            int c0 = bj * 64 + tx * 8 + cp * 2;
            float lo, hi;
            unpack_ff(acc[rr][cp], lo, hi);
            if (r0 < MM && c0 < MM)
                *(float2*)&S[(size_t)r0 * MM + c0] = make_float2(lo, hi);
            if (bi != bj && r0 < MM && c0 < MM) {
                S[(size_t)c0 * MM + r0] = lo;
                S[(size_t)(c0 + 1) * MM + r0] = hi;
            }
        }
    }
}

// ---- top-10 per row, packed-key (value desc, index asc) — round-1 proven ----
__global__ __launch_bounds__(256) void topk_kernel() {
    int warp = threadIdx.x >> 5, lane = threadIdx.x & 31;
    int row = blockIdx.x * 8 + warp;
    if (row >= NQ * MM) return;
    const float* Srow = g_S + (size_t)row * MM;

    unsigned long long key[13];
    #pragma unroll
    for (int t = 0; t < 13; t++) {
        int c = lane + t * 32;
        key[t] = (c < MM) ? pack_key(Srow[c], c) : 0ULL;
    }
    #pragma unroll
    for (int it = 0; it < KTOP; it++) {
        unsigned long long best = 0;
        #pragma unroll
        for (int t = 0; t < 13; t++) if (key[t] > best) best = key[t];
        #pragma unroll
        for (int off = 16; off > 0; off >>= 1) {
            unsigned long long o = __shfl_xor_sync(0xFFFFFFFFu, best, off);
            if (o > best) best = o;
        }
        if (lane == 0) {
            int c = (int)(0xFFFFFFFFu - (unsigned int)(best & 0xFFFFFFFFu));
            g_idx[row * KTOP + it] = c;
            g_vals[row * KTOP + it] = unordf((unsigned int)(best >> 32));
        }
        #pragma unroll
        for (int t = 0; t < 13; t++) if (key[t] == best) key[t] = 0ULL;
    }
}

// ---- x_dba + res_top (round-1 proven math; MPAD stride only) ----------------
__global__ __launch_bounds__(128) void xdba_kernel(const float* __restrict__ Qm,
                                                   float* __restrict__ out, int full) {
    int m = blockIdx.x, q = blockIdx.y, tid = threadIdx.x;
    int row = q * MM + m;
    __shared__ int sidx[KTOP];
    __shared__ float sval[KTOP];
    __shared__ float red[128];
    if (tid < KTOP) {
        sidx[tid] = g_idx[row * KTOP + tid];
        sval[tid] = g_vals[row * KTOP + tid];
    }
    __syncthreads();

    const float4* Xq = (const float4*)(g_Xs + (size_t)q * MPAD * DIM);
    float4 a = Xq[(size_t)sidx[0] * (DIM / 4) + tid];  // w0 = 1.0
    float sumw = 1.0f;
    #pragma unroll
    for (int k = 1; k < KTOP; k++) {
        float w = __fmul_rn(BETA, sval[k]);
        sumw = __fadd_rn(sumw, w);
        float4 v = Xq[(size_t)sidx[k] * (DIM / 4) + tid];
        a.x = __fadd_rn(a.x, __fmul_rn(w, v.x));
        a.y = __fadd_rn(a.y, __fmul_rn(w, v.y));
        a.z = __fadd_rn(a.z, __fmul_rn(w, v.z));
        a.w = __fadd_rn(a.w, __fmul_rn(w, v.w));
    }
    a.x = __fdiv_rn(a.x, sumw);
    a.y = __fdiv_rn(a.y, sumw);
    a.z = __fdiv_rn(a.z, sumw);
    a.w = __fdiv_rn(a.w, sumw);

    if (full)
        *(float4*)(out + OFF_XDBA + (size_t)row * DIM + tid * 4) = a;

    float4 qv = ((const float4*)Qm)[(size_t)q * (DIM / 4) + tid];
    red[tid] = a.x * qv.x + a.y * qv.y + a.z * qv.z + a.w * qv.w;
    __syncthreads();
    #pragma unroll
    for (int s = 64; s > 0; s >>= 1) {
        if (tid < s) red[tid] += red[tid + s];
        __syncthreads();
    }
    if (tid == 0) {
        g_restop[row] = red[0];
        if (full) out[OFF_RESTOP + row] = red[0];
    }
}

// ---- stable descending sort (bitonic 512) + final outputs -------------------
__global__ __launch_bounds__(512) void sort_kernel(float* __restrict__ out,
                                                   int full, int out_size) {
    int q = blockIdx.x, tid = threadIdx.x;
    __shared__ unsigned long long sk[512];
    sk[tid] = (tid < MM) ? pack_key(g_restop[q * MM + tid], tid) : 0ULL;
    __syncthreads();
    for (int k = 2; k <= 512; k <<= 1) {
        for (int j = k >> 1; j > 0; j >>= 1) {
            int ixj = tid ^ j;
            if (ixj > tid) {
                unsigned long long a = sk[tid], b = sk[ixj];
                bool desc = (tid & k) == 0;
                if (desc ? (a < b) : (a > b)) { sk[tid] = b; sk[ixj] = a; }
            }
            __syncthreads();
        }
    }
    if (tid < MM) {
        unsigned int msel = 0xFFFFFFFFu - (unsigned int)(sk[tid] & 0xFFFFFFFFu);
        int o0 = q * MM + tid;
        if (o0 < out_size) out[OFF_RERANK + o0] = (float)g_rt[q * MM + msel];
        if (full) out[OFF_PRE + o0] = (float)msel;
    }
}

extern "C" void kernel_launch(void* const* d_in, const int* in_sizes, int n_in,
                              void* d_out, int out_size) {
    const float* X  = (const float*)d_in[0];
    const float* Qm = (const float*)d_in[1];
    const void*  rk = d_in[2];
    float* out = (float*)d_out;
    int full = (out_size >= FULL_OUT) ? 1 : 0;

    probe_kernel<<<1, 256>>>((const int*)rk);
    gather_kernel<<<dim3(MPAD, NQ), 128>>>(X, rk);
    gemm_kernel<<<dim3(28, NQ), 64>>>();
    topk_kernel<<<(NQ * MM + 7) / 8, 256>>>();
    xdba_kernel<<<dim3(MM, NQ), 128>>>(Qm, out, full);
    sort_kernel<<<NQ, 512>>>(out, full, out_size);
}

// round 6
// speedup vs baseline: 1.1388x; 1.1388x over previous
#include <cuda_runtime.h>
#include <cstdint>
#include <math_constants.h>

// ---------------------------------------------------------------------------
// MDescAug: per-query candidate reranking with descriptor augmentation.
//   X: [50000,512] f32,  Q: [100,512] f32,  ranks: [50000,100] i32/i64 (probed)
// Output f32 concat: rerank_final[100,400], res_top[100,400], pre[100,400],
//                    x_dba[100,400,512]
// GEMM: serial ascending-k fp32 FMA chains (bitwise == reference bracketing),
// FFMA2 (fma.rn.f32x2) packing 2 output columns; 256-thread round-1 shape.
// ---------------------------------------------------------------------------

#define NDB  50000
#define NQ   100
#define DIM  512
#define MM   400
#define MPAD 448              // 7 * 64, zero-padded rows
#define KTOP 10
#define BETA 0.15f

#define OFF_RERANK 0
#define OFF_RESTOP 40000
#define OFF_PRE    80000
#define OFF_XDBA   120000
#define FULL_OUT   20600000

// Scratch (device globals; no allocation allowed)
__device__ float g_Xs[(size_t)NQ * MPAD * DIM];   // gathered (padded)
__device__ float g_S[(size_t)NQ * MM * MM];       // similarity matrices
__device__ int   g_rt[NQ * MM];
__device__ int   g_idx[NQ * MM * KTOP];
__device__ float g_vals[NQ * MM * KTOP];
__device__ float g_restop[NQ * MM];
__device__ int   g_is64;

// ---- order-preserving float<->uint ------------------------------------------
__device__ __forceinline__ unsigned int ordf(float f) {
    unsigned int u = __float_as_uint(f);
    return (u & 0x80000000u) ? ~u : (u | 0x80000000u);
}
__device__ __forceinline__ unsigned long long pack_key(float v, int idx) {
    return ((unsigned long long)ordf(v) << 32) |
           (unsigned long long)(0xFFFFFFFFu - (unsigned int)idx);
}

// ---- probe: int64 vs int32 ranks --------------------------------------------
__global__ void probe_kernel(const int* __restrict__ r) {
    __shared__ int cnt;
    if (threadIdx.x == 0) cnt = 0;
    __syncthreads();
    int nz = 0;
    for (int i = threadIdx.x; i < 1024; i += blockDim.x)
        nz += (r[2 * i + 1] != 0);
    atomicAdd(&cnt, nz);
    __syncthreads();
    if (threadIdx.x == 0) g_is64 = (cnt < 100) ? 1 : 0;
}

// ---- gather Xs[q][m][:] = X[ranks[m][q]][:]; zero-pad rows 400..447 ---------
__global__ __launch_bounds__(128) void gather_kernel(const float* __restrict__ X,
                                                     const void* __restrict__ ranks) {
    int m = blockIdx.x, q = blockIdx.y, tid = threadIdx.x;
    float4* dst = (float4*)(g_Xs + ((size_t)q * MPAD + m) * DIM);
    if (m >= MM) {
        dst[tid] = make_float4(0.f, 0.f, 0.f, 0.f);
        return;
    }
    int rid;
    if (g_is64) rid = (int)((const long long*)ranks)[(size_t)m * NQ + q];
    else        rid = ((const int*)ranks)[(size_t)m * NQ + q];
    if (tid == 0) g_rt[q * MM + m] = rid;
    const float4* src = (const float4*)(X + (size_t)rid * DIM);
    dst[tid] = src[tid];
}

// ---- packed fp32 helpers ----------------------------------------------------
__device__ __forceinline__ unsigned long long pack_ff(float lo, float hi) {
    unsigned long long r;
    asm("mov.b64 %0, {%1, %2};" : "=l"(r) : "f"(lo), "f"(hi));
    return r;
}
__device__ __forceinline__ void unpack_ff(unsigned long long v, float& lo, float& hi) {
    asm("mov.b64 {%0, %1}, %2;" : "=f"(lo), "=f"(hi) : "l"(v));
}
// Two independent IEEE fp32 FMAs (FFMA2). Each lane = exact fp32 fma chain.
__device__ __forceinline__ void ffma2(unsigned long long& acc,
                                      unsigned long long a, unsigned long long b) {
    asm("fma.rn.f32x2 %0, %1, %2, %0;" : "+l"(acc) : "l"(a), "l"(b));
}

// ---- batched symmetric GEMM: S_q = Xs_q * Xs_q^T ----------------------------
// 64x64 tile, BK=16, 256 threads (16x16 grid), per-thread 4 rows x 2 col-pairs.
// Serial k-ascending fp32 chains -> bitwise identical to scalar FFMA GEMM.
#define ASD 136   // words per k-slice of A-dup
#define BSD 72    // words per k-slice of B
__device__ __forceinline__ int wA(int k, int r) {
    return k * ASD + 2 * r + (((k >> 2) & 3) << 3);
}
__device__ __forceinline__ int wB(int k, int c) {
    return k * BSD + c + 2 * (c >> 5) + (((k >> 2) & 3) << 3);
}

__global__ __launch_bounds__(256) void gemm_kernel() {
    __shared__ __align__(16) float Ad[2192];  // A duplicated {a,a}, swizzled
    __shared__ __align__(16) float Bb[1172];  // B scalar, swizzled

    int p = blockIdx.x, q = blockIdx.y;
    int bi = 0, bj = 0;
    {
        int t = 0;
        #pragma unroll
        for (int i = 0; i < 7; i++) {
            int c = 7 - i;
            if (p < t + c) { bi = i; bj = i + (p - t); break; }
            t += c;
        }
    }
    const float* Xq = g_Xs + (size_t)q * MPAD * DIM;
    const float* Ap = Xq + (size_t)bi * 64 * DIM;
    const float* Bp = Xq + (size_t)bj * 64 * DIM;

    int tid = threadIdx.x;
    int tx = tid & 15, ty = tid >> 4;      // 16x16 compute grid
    int lrow = tid >> 2, lseg = tid & 3;   // staging: 4 threads/row

    unsigned long long acc[4][2];
    #pragma unroll
    for (int r = 0; r < 4; r++) { acc[r][0] = 0ULL; acc[r][1] = 0ULL; }

    const float4* Ag = (const float4*)(Ap + (size_t)lrow * DIM + lseg * 4);
    const float4* Bg = (const float4*)(Bp + (size_t)lrow * DIM + lseg * 4);

    float4 pa = Ag[0], pb = Bg[0];

    for (int ch = 0; ch < 32; ch++) {
        __syncthreads();
        {
            float a4[4] = {pa.x, pa.y, pa.z, pa.w};
            float b4[4] = {pb.x, pb.y, pb.z, pb.w};
            #pragma unroll
            for (int j = 0; j < 4; j++) {
                int k = lseg * 4 + j;
                *(unsigned long long*)&Ad[wA(k, lrow)] = pack_ff(a4[j], a4[j]);
                Bb[wB(k, lrow)] = b4[j];
            }
        }
        __syncthreads();
        if (ch < 31) { pa = Ag[(ch + 1) * 4]; pb = Bg[(ch + 1) * 4]; }
        #pragma unroll
        for (int kk = 0; kk < 16; kk++) {
            unsigned long long af[4], bf[2];
            #pragma unroll
            for (int rr = 0; rr < 4; rr++)
                af[rr] = *(const unsigned long long*)&Ad[wA(kk, ty * 4 + rr)];
            #pragma unroll
            for (int cp = 0; cp < 2; cp++)
                bf[cp] = *(const unsigned long long*)&Bb[wB(kk, tx * 4 + cp * 2)];
            #pragma unroll
            for (int rr = 0; rr < 4; rr++) {
                ffma2(acc[rr][0], af[rr], bf[0]);
                ffma2(acc[rr][1], af[rr], bf[1]);
            }
        }
    }

    float* S = g_S + (size_t)q * MM * MM;
    #pragma unroll
    for (int rr = 0; rr < 4; rr++) {
        int r0 = bi * 64 + ty * 4 + rr;
        #pragma unroll
        for (int cp = 0; cp < 2; cp++) {
            int c0 = bj * 64 + tx * 4 + cp * 2;
            float lo, hi;
            unpack_ff(acc[rr][cp], lo, hi);
            if (r0 < MM && c0 < MM) {
                *(float2*)&S[(size_t)r0 * MM + c0] = make_float2(lo, hi);
                if (bi != bj) {
                    S[(size_t)c0 * MM + r0] = lo;
                    S[(size_t)(c0 + 1) * MM + r0] = hi;
                }
            }
        }
    }
}

// ---- top-10 per row (float compares on FMA pipe; value desc, index asc) -----
__global__ __launch_bounds__(256) void topk_kernel() {
    int warp = threadIdx.x >> 5, lane = threadIdx.x & 31;
    int row = blockIdx.x * 8 + warp;
    if (row >= NQ * MM) return;
    const float* Srow = g_S + (size_t)row * MM;

    float v[13];
    #pragma unroll
    for (int t = 0; t < 13; t++) {
        int c = lane + t * 32;
        v[t] = (c < MM) ? Srow[c] : -CUDART_INF_F;
    }
    #pragma unroll
    for (int it = 0; it < KTOP; it++) {
        float m = v[0];
        #pragma unroll
        for (int t = 1; t < 13; t++) m = fmaxf(m, v[t]);
        #pragma unroll
        for (int off = 16; off > 0; off >>= 1)
            m = fmaxf(m, __shfl_xor_sync(0xFFFFFFFFu, m, off));
        int c = 0x7FFFFFFF;
        #pragma unroll
        for (int t = 12; t >= 0; t--)
            if (v[t] == m) c = t * 32 + lane;
        #pragma unroll
        for (int off = 16; off > 0; off >>= 1)
            c = min(c, __shfl_xor_sync(0xFFFFFFFFu, c, off));
        if (lane == 0) {
            g_idx[row * KTOP + it] = c;
            g_vals[row * KTOP + it] = m;
        }
        #pragma unroll
        for (int t = 0; t < 13; t++)
            if (t * 32 + lane == c) v[t] = -CUDART_INF_F;
    }
}

// ---- x_dba + res_top (round-1 proven math) ----------------------------------
__global__ __launch_bounds__(128) void xdba_kernel(const float* __restrict__ Qm,
                                                   float* __restrict__ out, int full) {
    int m = blockIdx.x, q = blockIdx.y, tid = threadIdx.x;
    int row = q * MM + m;
    __shared__ int sidx[KTOP];
    __shared__ float sval[KTOP];
    __shared__ float red[128];
    if (tid < KTOP) {
        sidx[tid] = g_idx[row * KTOP + tid];
        sval[tid] = g_vals[row * KTOP + tid];
    }
    __syncthreads();

    const float4* Xq = (const float4*)(g_Xs + (size_t)q * MPAD * DIM);
    float4 a = Xq[(size_t)sidx[0] * (DIM / 4) + tid];  // w0 = 1.0
    float sumw = 1.0f;
    #pragma unroll
    for (int k = 1; k < KTOP; k++) {
        float w = __fmul_rn(BETA, sval[k]);
        sumw = __fadd_rn(sumw, w);
        float4 v = Xq[(size_t)sidx[k] * (DIM / 4) + tid];
        a.x = __fadd_rn(a.x, __fmul_rn(w, v.x));
        a.y = __fadd_rn(a.y, __fmul_rn(w, v.y));
        a.z = __fadd_rn(a.z, __fmul_rn(w, v.z));
        a.w = __fadd_rn(a.w, __fmul_rn(w, v.w));
    }
    a.x = __fdiv_rn(a.x, sumw);
    a.y = __fdiv_rn(a.y, sumw);
    a.z = __fdiv_rn(a.z, sumw);
    a.w = __fdiv_rn(a.w, sumw);

    if (full)
        *(float4*)(out + OFF_XDBA + (size_t)row * DIM + tid * 4) = a;

    float4 qv = ((const float4*)Qm)[(size_t)q * (DIM / 4) + tid];
    red[tid] = a.x * qv.x + a.y * qv.y + a.z * qv.z + a.w * qv.w;
    __syncthreads();
    #pragma unroll
    for (int s = 64; s > 0; s >>= 1) {
        if (tid < s) red[tid] += red[tid + s];
        __syncthreads();
    }
    if (tid == 0) {
        g_restop[row] = red[0];
        if (full) out[OFF_RESTOP + row] = red[0];
    }
}

// ---- stable descending sort (bitonic 512) + final outputs -------------------
__global__ __launch_bounds__(512) void sort_kernel(float* __restrict__ out,
                                                   int full, int out_size) {
    int q = blockIdx.x, tid = threadIdx.x;
    __shared__ unsigned long long sk[512];
    sk[tid] = (tid < MM) ? pack_key(g_restop[q * MM + tid], tid) : 0ULL;
    __syncthreads();
    for (int k = 2; k <= 512; k <<= 1) {
        for (int j = k >> 1; j > 0; j >>= 1) {
            int ixj = tid ^ j;
            if (ixj > tid) {
                unsigned long long a = sk[tid], b = sk[ixj];
                bool desc = (tid & k) == 0;
                if (desc ? (a < b) : (a > b)) { sk[tid] = b; sk[ixj] = a; }
            }
            __syncthreads();
        }
    }
    if (tid < MM) {
        unsigned int msel = 0xFFFFFFFFu - (unsigned int)(sk[tid] & 0xFFFFFFFFu);
        int o0 = q * MM + tid;
        if (o0 < out_size) out[OFF_RERANK + o0] = (float)g_rt[q * MM + msel];
        if (full) out[OFF_PRE + o0] = (float)msel;
    }
}

extern "C" void kernel_launch(void* const* d_in, const int* in_sizes, int n_in,
                              void* d_out, int out_size) {
    const float* X  = (const float*)d_in[0];
    const float* Qm = (const float*)d_in[1];
    const void*  rk = d_in[2];
    float* out = (float*)d_out;
    int full = (out_size >= FULL_OUT) ? 1 : 0;

    probe_kernel<<<1, 256>>>((const int*)rk);
    gather_kernel<<<dim3(MPAD, NQ), 128>>>(X, rk);
    gemm_kernel<<<dim3(28, NQ), 256>>>();
    topk_kernel<<<(NQ * MM + 7) / 8, 256>>>();
    xdba_kernel<<<dim3(MM, NQ), 128>>>(Qm, out, full);
    sort_kernel<<<NQ, 512>>>(out, full, out_size);
}